// round 1
// baseline (speedup 1.0000x reference)
#include <cuda_runtime.h>
#include <math.h>

#define B_  4
#define S_  2048
#define D_  1024
#define H_  16
#define HD_ 64
#define NROWS (B_*S_)   // 8192

// Intermediate buffers (allocation-free scratch, per harness rules)
__device__ float g_qh[(size_t)B_*H_*S_*HD_];   // [B,H,S,HD]
__device__ float g_kh[(size_t)B_*H_*S_*HD_];
__device__ float g_vh[(size_t)B_*H_*S_*HD_];
__device__ float g_y [(size_t)B_*S_*D_];       // [B,S,D]

// ---------------------------------------------------------------------------
// GEMM: out = relu(X @ W^T + bias).  X:[NROWS,D], W:[D,D] row-major.
// SPLIT=true  -> write head-split layout [B,H,S,HD]
// SPLIT=false -> write row-major [NROWS, D]
// 128x128x8 tile, 256 threads, 8x8 per thread.
// ---------------------------------------------------------------------------
template<bool SPLIT>
__global__ __launch_bounds__(256, 2)
void proj_kernel(const float* __restrict__ X, const float* __restrict__ W,
                 const float* __restrict__ bias, float* __restrict__ out)
{
    const int BM = 128, BN = 128, BK = 8;
    __shared__ float As[BK][BM];
    __shared__ float Bs[BK][BN];

    const int t = threadIdx.x;
    const int rowBase = blockIdx.y * BM;
    const int colBase = blockIdx.x * BN;

    const int lr = t >> 1;          // 0..127
    const int lc = (t & 1) * 4;     // 0 or 4

    const float* Xptr = X + (size_t)(rowBase + lr) * D_ + lc;
    const float* Wptr = W + (size_t)(colBase + lr) * D_ + lc;

    float acc[8][8];
    #pragma unroll
    for (int i = 0; i < 8; i++)
        #pragma unroll
        for (int j = 0; j < 8; j++) acc[i][j] = 0.f;

    const int tx = t & 15;   // col group
    const int ty = t >> 4;   // row group

    for (int k0 = 0; k0 < D_; k0 += BK) {
        float4 av = *(const float4*)(Xptr + k0);
        float4 bv = *(const float4*)(Wptr + k0);
        __syncthreads();
        As[lc + 0][lr] = av.x; As[lc + 1][lr] = av.y;
        As[lc + 2][lr] = av.z; As[lc + 3][lr] = av.w;
        Bs[lc + 0][lr] = bv.x; Bs[lc + 1][lr] = bv.y;
        Bs[lc + 2][lr] = bv.z; Bs[lc + 3][lr] = bv.w;
        __syncthreads();

        #pragma unroll
        for (int k = 0; k < BK; k++) {
            float a[8], b[8];
            *(float4*)(a)     = *(const float4*)&As[k][ty * 8];
            *(float4*)(a + 4) = *(const float4*)&As[k][ty * 8 + 4];
            *(float4*)(b)     = *(const float4*)&Bs[k][tx * 8];
            *(float4*)(b + 4) = *(const float4*)&Bs[k][tx * 8 + 4];
            #pragma unroll
            for (int i = 0; i < 8; i++)
                #pragma unroll
                for (int j = 0; j < 8; j++)
                    acc[i][j] += a[i] * b[j];
        }
    }

    #pragma unroll
    for (int j = 0; j < 8; j++) {
        const int col = colBase + tx * 8 + j;
        const float bb = bias[col];
        #pragma unroll
        for (int i = 0; i < 8; i++) {
            const int row = rowBase + ty * 8 + i;
            float v = acc[i][j] + bb;
            v = v > 0.f ? v : 0.f;
            if (SPLIT) {
                const int h  = col >> 6, hd = col & 63;
                const int b  = row >> 11, s = row & 2047;  // S_=2048
                out[((size_t)((b * H_ + h) * S_) + s) * HD_ + hd] = v;
            } else {
                out[(size_t)row * D_ + col] = v;
            }
        }
    }
}

// ---------------------------------------------------------------------------
// Flash-style attention. One q-row per thread; 256 threads -> 256 q-rows per
// block. K/V tiles of 64 rows staged in smem, broadcast LDS reads.
// Writes y in [B,S,D] layout (head-merged).
// ---------------------------------------------------------------------------
__global__ __launch_bounds__(256, 1)
void attn_kernel()
{
    __shared__ float Ks[64][64];
    __shared__ float Vs[64][64];

    const int bh   = blockIdx.y;                         // 0..B*H-1
    const int qrow = blockIdx.x * 256 + threadIdx.x;     // 0..S-1

    const float* qp = g_qh + ((size_t)bh * S_ + qrow) * HD_;
    float q[64];
    #pragma unroll
    for (int d4 = 0; d4 < 16; d4++) {
        float4 v = ((const float4*)qp)[d4];
        q[4*d4+0] = v.x; q[4*d4+1] = v.y; q[4*d4+2] = v.z; q[4*d4+3] = v.w;
    }

    float O[64];
    #pragma unroll
    for (int d = 0; d < 64; d++) O[d] = 0.f;
    float m = -1e30f, l = 0.f;

    const int t  = threadIdx.x;
    const int lr = t >> 2;           // 0..63 tile row
    const int lc = (t & 3) * 16;     // 0,16,32,48

    for (int kt = 0; kt < S_; kt += 64) {
        const float4* kp = (const float4*)(g_kh + ((size_t)bh * S_ + kt + lr) * HD_ + lc);
        const float4* vp = (const float4*)(g_vh + ((size_t)bh * S_ + kt + lr) * HD_ + lc);
        __syncthreads();
        #pragma unroll
        for (int u = 0; u < 4; u++) {
            ((float4*)&Ks[lr][lc])[u] = kp[u];
            ((float4*)&Vs[lr][lc])[u] = vp[u];
        }
        __syncthreads();

        #pragma unroll 2
        for (int j = 0; j < 64; j++) {
            float s = 0.f;
            #pragma unroll
            for (int d4 = 0; d4 < 16; d4++) {
                float4 kv = ((const float4*)&Ks[j][0])[d4];
                s += q[4*d4+0]*kv.x + q[4*d4+1]*kv.y
                   + q[4*d4+2]*kv.z + q[4*d4+3]*kv.w;
            }
            s *= 0.125f;   // 1/sqrt(HD)

            if (s > m) {
                const float corr = __expf(m - s);
                l *= corr;
                #pragma unroll
                for (int d = 0; d < 64; d++) O[d] *= corr;
                m = s;
            }
            const float p = __expf(s - m);
            l += p;
            #pragma unroll
            for (int d4 = 0; d4 < 16; d4++) {
                float4 vv = ((const float4*)&Vs[j][0])[d4];
                O[4*d4+0] += p * vv.x; O[4*d4+1] += p * vv.y;
                O[4*d4+2] += p * vv.z; O[4*d4+3] += p * vv.w;
            }
        }
    }

    const float inv = 1.f / l;
    const int b = bh >> 4, h = bh & 15;   // H_=16
    float* yp = g_y + ((size_t)(b * S_ + qrow)) * D_ + h * HD_;
    #pragma unroll
    for (int d4 = 0; d4 < 16; d4++) {
        float4 o;
        o.x = O[4*d4+0] * inv; o.y = O[4*d4+1] * inv;
        o.z = O[4*d4+2] * inv; o.w = O[4*d4+3] * inv;
        ((float4*)yp)[d4] = o;
    }
}

// ---------------------------------------------------------------------------
extern "C" void kernel_launch(void* const* d_in, const int* in_sizes, int n_in,
                              void* d_out, int out_size)
{
    const float* q  = (const float*)d_in[0];
    const float* k  = (const float*)d_in[1];
    const float* v  = (const float*)d_in[2];
    const float* Wq = (const float*)d_in[3];
    const float* bq = (const float*)d_in[4];
    const float* Wk = (const float*)d_in[5];
    const float* bk = (const float*)d_in[6];
    const float* Wv = (const float*)d_in[7];
    const float* bv = (const float*)d_in[8];
    const float* Wo = (const float*)d_in[9];
    const float* bo = (const float*)d_in[10];
    float* out = (float*)d_out;

    float *gqh, *gkh, *gvh, *gy;
    cudaGetSymbolAddress((void**)&gqh, g_qh);
    cudaGetSymbolAddress((void**)&gkh, g_kh);
    cudaGetSymbolAddress((void**)&gvh, g_vh);
    cudaGetSymbolAddress((void**)&gy,  g_y);

    dim3 gridP(D_ / 128, NROWS / 128);   // (8, 64)
    dim3 blockP(256);

    proj_kernel<true><<<gridP, blockP>>>(q, Wq, bq, gqh);
    proj_kernel<true><<<gridP, blockP>>>(k, Wk, bk, gkh);
    proj_kernel<true><<<gridP, blockP>>>(v, Wv, bv, gvh);

    dim3 gridA(S_ / 256, B_ * H_);       // (8, 64)
    attn_kernel<<<gridA, 256>>>();

    proj_kernel<false><<<gridP, blockP>>>(gy, Wo, bo, out);
}

// round 3
// speedup vs baseline: 1.7699x; 1.7699x over previous
#include <cuda_runtime.h>
#include <cuda_bf16.h>
#include <math.h>
#include <stdint.h>

#define B_  4
#define S_  2048
#define D_  1024
#define H_  16
#define HD_ 64
#define NROWS (B_*S_)   // 8192

// Intermediate buffers (allocation-free scratch)
__device__ float g_qh[(size_t)B_*H_*S_*HD_];   // [B,H,S,HD]
__device__ float g_kh[(size_t)B_*H_*S_*HD_];
__device__ float g_vh[(size_t)B_*H_*S_*HD_];
__device__ float g_y [(size_t)B_*S_*D_];       // [B,S,D]

// ===========================================================================
// Tensor-core projection: out = relu(X @ W^T + b), fp32 in/out,
// bf16x3 split (Ah*Bh + Ah*Bl + Al*Bh) for fp32-class accuracy.
// Tile 128x128xK32, 256 threads (8 warps, warp tile 64x32), mma.m16n8k16.
// ===========================================================================

#define TSTR 40   // smem tile row stride in bf16 elems (80B: conflict-free ldmatrix)

__device__ __forceinline__ uint32_t smem_u32(const void* p) {
    return (uint32_t)__cvta_generic_to_shared(p);
}

__device__ __forceinline__ void ldmx4(uint32_t* d, uint32_t addr) {
    asm volatile("ldmatrix.sync.aligned.m8n8.x4.shared.b16 {%0,%1,%2,%3}, [%4];"
                 : "=r"(d[0]), "=r"(d[1]), "=r"(d[2]), "=r"(d[3]) : "r"(addr));
}
__device__ __forceinline__ void ldmx2(uint32_t* d, uint32_t addr) {
    asm volatile("ldmatrix.sync.aligned.m8n8.x2.shared.b16 {%0,%1}, [%2];"
                 : "=r"(d[0]), "=r"(d[1]) : "r"(addr));
}
__device__ __forceinline__ void mma16816(float* c, const uint32_t* a, const uint32_t* b) {
    asm volatile("mma.sync.aligned.m16n8k16.row.col.f32.bf16.bf16.f32 "
                 "{%0,%1,%2,%3}, {%4,%5,%6,%7}, {%8,%9}, {%0,%1,%2,%3};"
                 : "+f"(c[0]), "+f"(c[1]), "+f"(c[2]), "+f"(c[3])
                 : "r"(a[0]), "r"(a[1]), "r"(a[2]), "r"(a[3]), "r"(b[0]), "r"(b[1]));
}

__device__ __forceinline__ void split_store(__nv_bfloat16* hi, __nv_bfloat16* lo, float4 v) {
    float f[4] = {v.x, v.y, v.z, v.w};
    __nv_bfloat162 h01, h23, l01, l23;
    __nv_bfloat16 h;
    h = __float2bfloat16(f[0]); h01.x = h; l01.x = __float2bfloat16(f[0] - __bfloat162float(h));
    h = __float2bfloat16(f[1]); h01.y = h; l01.y = __float2bfloat16(f[1] - __bfloat162float(h));
    h = __float2bfloat16(f[2]); h23.x = h; l23.x = __float2bfloat16(f[2] - __bfloat162float(h));
    h = __float2bfloat16(f[3]); h23.y = h; l23.y = __float2bfloat16(f[3] - __bfloat162float(h));
    ((__nv_bfloat162*)hi)[0] = h01; ((__nv_bfloat162*)hi)[1] = h23;
    ((__nv_bfloat162*)lo)[0] = l01; ((__nv_bfloat162*)lo)[1] = l23;
}

template<bool SPLIT>
__global__ __launch_bounds__(256)
void proj_mma(const float* __restrict__ X, const float* __restrict__ W,
              const float* __restrict__ bias, float* __restrict__ out)
{
    __shared__ __nv_bfloat16 Ah[128*TSTR], Al[128*TSTR];
    __shared__ __nv_bfloat16 Bh[128*TSTR], Bl[128*TSTR];

    const int t    = threadIdx.x;
    const int lane = t & 31;
    const int warp = t >> 5;
    const int wm   = warp & 1;     // 0..1  (64-row group)
    const int wn   = warp >> 1;    // 0..3  (32-col group)

    const int rowBase = blockIdx.y * 128;
    const int colBase = blockIdx.x * 128;

    // loader mapping: 4 iterations, each thread one float4 of X and one of W
    const int ldRow = t >> 3;          // 0..31 (+32*i)
    const int ldCol = (t & 7) * 4;     // 0..28

    float acc[4][4][4];
    #pragma unroll
    for (int i = 0; i < 4; i++)
        #pragma unroll
        for (int j = 0; j < 4; j++)
            #pragma unroll
            for (int f = 0; f < 4; f++) acc[i][j][f] = 0.f;

    for (int k0 = 0; k0 < D_; k0 += 32) {
        __syncthreads();
        #pragma unroll
        for (int i = 0; i < 4; i++) {
            const int r = ldRow + 32 * i;
            float4 xv = *(const float4*)(X + (size_t)(rowBase + r) * D_ + k0 + ldCol);
            float4 wv = *(const float4*)(W + (size_t)(colBase + r) * D_ + k0 + ldCol);
            split_store(&Ah[r*TSTR + ldCol], &Al[r*TSTR + ldCol], xv);
            split_store(&Bh[r*TSTR + ldCol], &Bl[r*TSTR + ldCol], wv);
        }
        __syncthreads();

        #pragma unroll
        for (int ks = 0; ks < 32; ks += 16) {
            uint32_t ah[4][4], al[4][4], bh[4][2], bl[4][2];
            const int arow = wm*64 + (lane & 15);
            const int acol = ks + (lane >> 4) * 8;
            #pragma unroll
            for (int i = 0; i < 4; i++) {
                ldmx4(ah[i], smem_u32(&Ah[(arow + i*16)*TSTR + acol]));
                ldmx4(al[i], smem_u32(&Al[(arow + i*16)*TSTR + acol]));
            }
            const int brow = wn*32 + (lane & 7);
            const int bcol = ks + ((lane >> 3) & 1) * 8;
            #pragma unroll
            for (int j = 0; j < 4; j++) {
                ldmx2(bh[j], smem_u32(&Bh[(brow + j*8)*TSTR + bcol]));
                ldmx2(bl[j], smem_u32(&Bl[(brow + j*8)*TSTR + bcol]));
            }
            #pragma unroll
            for (int i = 0; i < 4; i++)
                #pragma unroll
                for (int j = 0; j < 4; j++) {
                    mma16816(acc[i][j], ah[i], bh[j]);
                    mma16816(acc[i][j], ah[i], bl[j]);
                    mma16816(acc[i][j], al[i], bh[j]);
                }
        }
    }

    // epilogue: bias + relu + store
    const int gID = lane >> 2, lmb = lane & 3;
    #pragma unroll
    for (int i = 0; i < 4; i++)
        #pragma unroll
        for (int j = 0; j < 4; j++)
            #pragma unroll
            for (int f = 0; f < 4; f++) {
                const int row = rowBase + wm*64 + i*16 + gID + ((f >= 2) ? 8 : 0);
                const int col = colBase + wn*32 + j*8 + lmb*2 + (f & 1);
                float v = acc[i][j][f] + bias[col];
                v = v > 0.f ? v : 0.f;
                if (SPLIT) {
                    const int hh = col >> 6, hd = col & 63;
                    const int bb = row >> 11, ss = row & (S_ - 1);
                    out[((size_t)((bb * H_ + hh) * S_) + ss) * HD_ + hd] = v;
                } else {
                    out[(size_t)row * D_ + col] = v;
                }
            }
}

// ===========================================================================
// Block-flash attention (fp32 FFMA, register tiled 4x4).
// Block = 64 q rows x full HD=64; 256 threads; K/V in 64-row tiles.
// Thread (ty=t>>4, tx=t&15): rows ty*4..+3, cols {tx, tx+16, tx+32, tx+48}.
// ===========================================================================
#define ASTR 68  // fp32 smem row stride (float4-aligned, low conflict)

__global__ __launch_bounds__(256, 2)
void attn_v2()
{
    extern __shared__ float sm[];
    float* Qs = sm;                 // [64][ASTR]
    float* Ks = Qs + 64*ASTR;
    float* Vs = Ks + 64*ASTR;
    float* Ps = Vs + 64*ASTR;

    const int bh    = blockIdx.y;                // 0..63
    const int qbase = blockIdx.x * 64;
    const int t  = threadIdx.x;
    const int tx = t & 15;
    const int ty = t >> 4;

    // load Q tile [64][64]
    {
        const float* qp = g_qh + ((size_t)bh * S_ + qbase) * HD_;
        #pragma unroll
        for (int i = 0; i < 4; i++) {
            int id = t + 256*i;
            int r = id >> 4, c = (id & 15) * 4;
            *(float4*)&Qs[r*ASTR + c] = *(const float4*)(qp + (size_t)r*HD_ + c);
        }
    }

    float O[4][4];
    #pragma unroll
    for (int i = 0; i < 4; i++)
        #pragma unroll
        for (int j = 0; j < 4; j++) O[i][j] = 0.f;
    float m_run[4], l_run[4];
    #pragma unroll
    for (int i = 0; i < 4; i++) { m_run[i] = -1e30f; l_run[i] = 0.f; }

    for (int kt = 0; kt < S_; kt += 64) {
        __syncthreads();
        {
            const float* kp = g_kh + ((size_t)bh * S_ + kt) * HD_;
            const float* vp = g_vh + ((size_t)bh * S_ + kt) * HD_;
            #pragma unroll
            for (int i = 0; i < 4; i++) {
                int id = t + 256*i;
                int r = id >> 4, c = (id & 15) * 4;
                *(float4*)&Ks[r*ASTR + c] = *(const float4*)(kp + (size_t)r*HD_ + c);
                *(float4*)&Vs[r*ASTR + c] = *(const float4*)(vp + (size_t)r*HD_ + c);
            }
        }
        __syncthreads();

        // ---- S = Q K^T (scaled) ----
        float s[4][4];
        #pragma unroll
        for (int i = 0; i < 4; i++)
            #pragma unroll
            for (int j = 0; j < 4; j++) s[i][j] = 0.f;

        #pragma unroll 4
        for (int kk = 0; kk < 64; kk += 4) {
            float a[4][4], b[4][4];
            #pragma unroll
            for (int i = 0; i < 4; i++)
                *(float4*)a[i] = *(const float4*)&Qs[(ty*4 + i)*ASTR + kk];
            #pragma unroll
            for (int j = 0; j < 4; j++)
                *(float4*)b[j] = *(const float4*)&Ks[(tx + 16*j)*ASTR + kk];
            #pragma unroll
            for (int u = 0; u < 4; u++)
                #pragma unroll
                for (int i = 0; i < 4; i++)
                    #pragma unroll
                    for (int j = 0; j < 4; j++)
                        s[i][j] += a[i][u] * b[j][u];
        }

        // ---- online softmax ----
        #pragma unroll
        for (int i = 0; i < 4; i++) {
            float mx = s[i][0];
            #pragma unroll
            for (int j = 1; j < 4; j++) mx = fmaxf(mx, s[i][j]);
            mx *= 0.125f;
            #pragma unroll
            for (int off = 1; off < 16; off <<= 1)
                mx = fmaxf(mx, __shfl_xor_sync(0xffffffffu, mx, off));
            const float mnew = fmaxf(m_run[i], mx);
            const float corr = __expf(m_run[i] - mnew);
            float rs = 0.f;
            #pragma unroll
            for (int j = 0; j < 4; j++) {
                float p = __expf(s[i][j] * 0.125f - mnew);
                Ps[(ty*4 + i)*ASTR + tx + 16*j] = p;
                rs += p;
            }
            #pragma unroll
            for (int off = 1; off < 16; off <<= 1)
                rs += __shfl_xor_sync(0xffffffffu, rs, off);
            l_run[i] = l_run[i] * corr + rs;
            m_run[i] = mnew;
            #pragma unroll
            for (int j = 0; j < 4; j++) O[i][j] *= corr;
        }
        __syncthreads();

        // ---- O += P V ----
        #pragma unroll 4
        for (int kk = 0; kk < 64; kk += 4) {
            float a[4][4];
            #pragma unroll
            for (int i = 0; i < 4; i++)
                *(float4*)a[i] = *(const float4*)&Ps[(ty*4 + i)*ASTR + kk];
            #pragma unroll
            for (int u = 0; u < 4; u++) {
                float b[4];
                #pragma unroll
                for (int j = 0; j < 4; j++) b[j] = Vs[(kk + u)*ASTR + tx + 16*j];
                #pragma unroll
                for (int i = 0; i < 4; i++)
                    #pragma unroll
                    for (int j = 0; j < 4; j++)
                        O[i][j] += a[i][u] * b[j];
            }
        }
    }

    // ---- write y [B,S,D] ----
    const int bb = bh >> 4, hh = bh & 15;
    #pragma unroll
    for (int i = 0; i < 4; i++) {
        const float inv = 1.f / l_run[i];
        float* yp = g_y + ((size_t)(bb * S_ + qbase + ty*4 + i)) * D_ + hh * HD_;
        #pragma unroll
        for (int j = 0; j < 4; j++) yp[tx + 16*j] = O[i][j] * inv;
    }
}

// ===========================================================================
extern "C" void kernel_launch(void* const* d_in, const int* in_sizes, int n_in,
                              void* d_out, int out_size)
{
    const float* q  = (const float*)d_in[0];
    const float* k  = (const float*)d_in[1];
    const float* v  = (const float*)d_in[2];
    const float* Wq = (const float*)d_in[3];
    const float* bq = (const float*)d_in[4];
    const float* Wk = (const float*)d_in[5];
    const float* bk = (const float*)d_in[6];
    const float* Wv = (const float*)d_in[7];
    const float* bv = (const float*)d_in[8];
    const float* Wo = (const float*)d_in[9];
    const float* bo = (const float*)d_in[10];
    float* out = (float*)d_out;

    float *gqh, *gkh, *gvh, *gy;
    cudaGetSymbolAddress((void**)&gqh, g_qh);
    cudaGetSymbolAddress((void**)&gkh, g_kh);
    cudaGetSymbolAddress((void**)&gvh, g_vh);
    cudaGetSymbolAddress((void**)&gy,  g_y);

    const int ASMEM = 4 * 64 * ASTR * sizeof(float);   // 69632 B
    static bool attr_done = false;
    if (!attr_done) {
        cudaFuncSetAttribute(attn_v2, cudaFuncAttributeMaxDynamicSharedMemorySize, ASMEM);
        attr_done = true;
    }

    dim3 gridP(D_ / 128, NROWS / 128);   // (8, 64)
    proj_mma<true><<<gridP, 256>>>(q, Wq, bq, gqh);
    proj_mma<true><<<gridP, 256>>>(k, Wk, bk, gkh);
    proj_mma<true><<<gridP, 256>>>(v, Wv, bv, gvh);

    attn_v2<<<dim3(S_/64, B_*H_), 256, ASMEM>>>();

    proj_mma<false><<<gridP, 256>>>(gy, Wo, bo, out);
}

// round 6
// speedup vs baseline: 3.3391x; 1.8866x over previous
#include <cuda_runtime.h>
#include <cuda_bf16.h>
#include <math.h>
#include <stdint.h>

#define B_  4
#define S_  2048
#define D_  1024
#define H_  16
#define HD_ 64
#define NROWS (B_*S_)                       // 8192
#define NPLANE ((size_t)B_*H_*S_*HD_)       // 8388608

// Scratch (allocation-free): projections write bf16 hi/lo planes, head-split.
__device__ __align__(16) __nv_bfloat16 g_q_hi[NPLANE], g_q_lo[NPLANE];
__device__ __align__(16) __nv_bfloat16 g_k_hi[NPLANE], g_k_lo[NPLANE];
__device__ __align__(16) __nv_bfloat16 g_v_hi[NPLANE], g_v_lo[NPLANE];
__device__ __align__(16) float g_y[(size_t)B_*S_*D_];

// ---------------------------------------------------------------------------
// Common PTX helpers
// ---------------------------------------------------------------------------
__device__ __forceinline__ uint32_t smem_u32(const void* p) {
    return (uint32_t)__cvta_generic_to_shared(p);
}
__device__ __forceinline__ void ldmx4(uint32_t* d, uint32_t addr) {
    asm volatile("ldmatrix.sync.aligned.m8n8.x4.shared.b16 {%0,%1,%2,%3}, [%4];"
                 : "=r"(d[0]), "=r"(d[1]), "=r"(d[2]), "=r"(d[3]) : "r"(addr));
}
__device__ __forceinline__ void ldmx4t(uint32_t* d, uint32_t addr) {
    asm volatile("ldmatrix.sync.aligned.m8n8.x4.trans.shared.b16 {%0,%1,%2,%3}, [%4];"
                 : "=r"(d[0]), "=r"(d[1]), "=r"(d[2]), "=r"(d[3]) : "r"(addr));
}
__device__ __forceinline__ void ldmx2(uint32_t* d, uint32_t addr) {
    asm volatile("ldmatrix.sync.aligned.m8n8.x2.shared.b16 {%0,%1}, [%2];"
                 : "=r"(d[0]), "=r"(d[1]) : "r"(addr));
}
__device__ __forceinline__ void mma16816(float* c, const uint32_t* a, const uint32_t* b) {
    asm volatile("mma.sync.aligned.m16n8k16.row.col.f32.bf16.bf16.f32 "
                 "{%0,%1,%2,%3}, {%4,%5,%6,%7}, {%8,%9}, {%0,%1,%2,%3};"
                 : "+f"(c[0]), "+f"(c[1]), "+f"(c[2]), "+f"(c[3])
                 : "r"(a[0]), "r"(a[1]), "r"(a[2]), "r"(a[3]), "r"(b[0]), "r"(b[1]));
}
__device__ __forceinline__ void cp16(void* dst, const void* src) {
    asm volatile("cp.async.cg.shared.global [%0], [%1], 16;"
                 :: "r"(smem_u32(dst)), "l"(src));
}
__device__ __forceinline__ void cpcommit() { asm volatile("cp.async.commit_group;"); }
__device__ __forceinline__ void cpwait0()  { asm volatile("cp.async.wait_group 0;"); }
__device__ __forceinline__ void cpwait1()  { asm volatile("cp.async.wait_group 1;"); }

// fp32 -> bf16 hi/lo pair (2 adjacent values packed into b32 regs)
__device__ __forceinline__ void pack2(float a, float b, uint32_t& hi, uint32_t& lo) {
    __nv_bfloat162 h = __floats2bfloat162_rn(a, b);
    float ra = a - __bfloat162float(h.x);
    float rb = b - __bfloat162float(h.y);
    __nv_bfloat162 l2 = __floats2bfloat162_rn(ra, rb);
    hi = *(uint32_t*)&h; lo = *(uint32_t*)&l2;
}

// ===========================================================================
// Tensor-core projection: relu(X @ W^T + b). fp32 in. bf16x3 compensated.
// SPLIT=true:  write bf16 hi/lo planes, head-split [B,H,S,HD]
// SPLIT=false: write fp32 row-major [NROWS, D] (final output)
// Tile 128x128xK32, 256 threads, warp tile 64x32.
// ===========================================================================
#define TSTR 40

__device__ __forceinline__ void split_store(__nv_bfloat16* hi, __nv_bfloat16* lo, float4 v) {
    float f[4] = {v.x, v.y, v.z, v.w};
    __nv_bfloat162 h01, h23, l01, l23;
    __nv_bfloat16 h;
    h = __float2bfloat16(f[0]); h01.x = h; l01.x = __float2bfloat16(f[0] - __bfloat162float(h));
    h = __float2bfloat16(f[1]); h01.y = h; l01.y = __float2bfloat16(f[1] - __bfloat162float(h));
    h = __float2bfloat16(f[2]); h23.x = h; l23.x = __float2bfloat16(f[2] - __bfloat162float(h));
    h = __float2bfloat16(f[3]); h23.y = h; l23.y = __float2bfloat16(f[3] - __bfloat162float(h));
    ((__nv_bfloat162*)hi)[0] = h01; ((__nv_bfloat162*)hi)[1] = h23;
    ((__nv_bfloat162*)lo)[0] = l01; ((__nv_bfloat162*)lo)[1] = l23;
}

template<bool SPLIT>
__global__ __launch_bounds__(256)
void proj_mma(const float* __restrict__ X, const float* __restrict__ W,
              const float* __restrict__ bias, float* __restrict__ outF,
              __nv_bfloat16* __restrict__ hiP, __nv_bfloat16* __restrict__ loP)
{
    __shared__ __nv_bfloat16 Ah[128*TSTR], Al[128*TSTR];
    __shared__ __nv_bfloat16 Bh[128*TSTR], Bl[128*TSTR];

    const int t = threadIdx.x, lane = t & 31, warp = t >> 5;
    const int wm = warp & 1, wn = warp >> 1;
    const int rowBase = blockIdx.y * 128, colBase = blockIdx.x * 128;
    const int ldRow = t >> 3, ldCol = (t & 7) * 4;

    float acc[4][4][4];
    #pragma unroll
    for (int i = 0; i < 4; i++)
        #pragma unroll
        for (int j = 0; j < 4; j++)
            #pragma unroll
            for (int f = 0; f < 4; f++) acc[i][j][f] = 0.f;

    for (int k0 = 0; k0 < D_; k0 += 32) {
        __syncthreads();
        #pragma unroll
        for (int i = 0; i < 4; i++) {
            const int r = ldRow + 32 * i;
            float4 xv = *(const float4*)(X + (size_t)(rowBase + r) * D_ + k0 + ldCol);
            float4 wv = *(const float4*)(W + (size_t)(colBase + r) * D_ + k0 + ldCol);
            split_store(&Ah[r*TSTR + ldCol], &Al[r*TSTR + ldCol], xv);
            split_store(&Bh[r*TSTR + ldCol], &Bl[r*TSTR + ldCol], wv);
        }
        __syncthreads();

        #pragma unroll
        for (int ks = 0; ks < 32; ks += 16) {
            uint32_t ah[4][4], al[4][4], bh[4][2], bl[4][2];
            const int arow = wm*64 + (lane & 15);
            const int acol = ks + (lane >> 4) * 8;
            #pragma unroll
            for (int i = 0; i < 4; i++) {
                ldmx4(ah[i], smem_u32(&Ah[(arow + i*16)*TSTR + acol]));
                ldmx4(al[i], smem_u32(&Al[(arow + i*16)*TSTR + acol]));
            }
            const int brow = wn*32 + (lane & 7);
            const int bcol = ks + ((lane >> 3) & 1) * 8;
            #pragma unroll
            for (int j = 0; j < 4; j++) {
                ldmx2(bh[j], smem_u32(&Bh[(brow + j*8)*TSTR + bcol]));
                ldmx2(bl[j], smem_u32(&Bl[(brow + j*8)*TSTR + bcol]));
            }
            #pragma unroll
            for (int i = 0; i < 4; i++)
                #pragma unroll
                for (int j = 0; j < 4; j++) {
                    mma16816(acc[i][j], ah[i], bh[j]);
                    mma16816(acc[i][j], ah[i], bl[j]);
                    mma16816(acc[i][j], al[i], bh[j]);
                }
        }
    }

    const int g = lane >> 2, lmb = lane & 3;
    #pragma unroll
    for (int i = 0; i < 4; i++)
        #pragma unroll
        for (int j = 0; j < 4; j++) {
            const int col = colBase + wn*32 + j*8 + lmb*2;
            const float b0 = bias[col], b1 = bias[col+1];
            #pragma unroll
            for (int r = 0; r < 2; r++) {
                const int row = rowBase + wm*64 + i*16 + g + 8*r;
                float v0 = acc[i][j][2*r+0] + b0;  v0 = v0 > 0.f ? v0 : 0.f;
                float v1 = acc[i][j][2*r+1] + b1;  v1 = v1 > 0.f ? v1 : 0.f;
                if (SPLIT) {
                    uint32_t hi, lo; pack2(v0, v1, hi, lo);
                    const int hh = col >> 6, hd = col & 63;
                    const int bb = row >> 11, ss = row & (S_ - 1);
                    const size_t idx = ((size_t)((bb*H_ + hh)*S_) + ss)*HD_ + hd;
                    *(uint32_t*)(hiP + idx) = hi;
                    *(uint32_t*)(loP + idx) = lo;
                } else {
                    float2 o; o.x = v0; o.y = v1;
                    *(float2*)(outF + (size_t)row * D_ + col) = o;
                }
            }
        }
}

// ===========================================================================
// Flash attention on tensor cores. CTA = 64 q rows, 4 warps (16 rows/warp).
// KV tiles of 64, double-buffered via cp.async. bf16x3 compensated QK^T & PV.
// ===========================================================================
#define KSTR 72
#define PL_  (64*KSTR)
#define STAGE_ (4*PL_)
#define NT_ (S_/64)

__global__ __launch_bounds__(128)
void attn_mma()
{
    extern __shared__ __nv_bfloat16 sm[];
    const int t = threadIdx.x, lane = t & 31, w = t >> 5;
    const int bh = blockIdx.y, qbase = blockIdx.x * 64;
    const int g = lane >> 2, lmb = lane & 3;

    __nv_bfloat16* st0 = sm;
    __nv_bfloat16* st1 = sm + STAGE_;

    const size_t base = (size_t)bh * S_;

    // prefetch KV tile 0 -> stage 0
    #pragma unroll
    for (int i = 0; i < 4; i++) {
        const int id = t + 128*i, r = id >> 3, c = (id & 7) * 8;
        const size_t go = (base + r) * HD_ + c;
        cp16(st0 + 0*PL_ + r*KSTR + c, g_k_hi + go);
        cp16(st0 + 1*PL_ + r*KSTR + c, g_k_lo + go);
        cp16(st0 + 2*PL_ + r*KSTR + c, g_v_hi + go);
        cp16(st0 + 3*PL_ + r*KSTR + c, g_v_lo + go);
    }
    cpcommit();
    // Q tile -> stage 1 (planes 0,1)
    #pragma unroll
    for (int i = 0; i < 4; i++) {
        const int id = t + 128*i, r = id >> 3, c = (id & 7) * 8;
        const size_t go = (base + qbase + r) * HD_ + c;
        cp16(st1 + 0*PL_ + r*KSTR + c, g_q_hi + go);
        cp16(st1 + 1*PL_ + r*KSTR + c, g_q_lo + go);
    }
    cpcommit();
    cpwait0();
    __syncthreads();

    // Q fragments (held in regs for whole kernel)
    uint32_t qh[4][4], ql[4][4];
    {
        const int arow = 16*w + (lane & 15);
        const int acol = (lane >> 4) * 8;
        #pragma unroll
        for (int kc = 0; kc < 4; kc++) {
            ldmx4(qh[kc], smem_u32(st1 + 0*PL_ + arow*KSTR + kc*16 + acol));
            ldmx4(ql[kc], smem_u32(st1 + 1*PL_ + arow*KSTR + kc*16 + acol));
        }
    }
    __syncthreads();   // stage1 free for KV tile 1

    float o[8][4];
    #pragma unroll
    for (int j = 0; j < 8; j++)
        #pragma unroll
        for (int f = 0; f < 4; f++) o[j][f] = 0.f;
    float m_run[2] = {-1e30f, -1e30f}, l_run[2] = {0.f, 0.f};

    const int krow = (lane & 7) + ((lane >> 4) & 1) * 8;   // K b-frag row
    const int kcsel = ((lane >> 3) & 1) * 8;               // K b-frag k-col half
    const int vrow = lane & 15;                            // V trans row
    const int vcsel = ((lane >> 4) & 1) * 8;               // V d-col half

    for (int it = 0; it < NT_; it++) {
        const int cur = it & 1;
        __nv_bfloat16* stc = cur ? st1 : st0;
        if (it + 1 < NT_) {
            __nv_bfloat16* d = cur ? st0 : st1;
            #pragma unroll
            for (int i = 0; i < 4; i++) {
                const int id = t + 128*i, r = id >> 3, c = (id & 7) * 8;
                const size_t go = (base + (size_t)(it+1)*64 + r) * HD_ + c;
                cp16(d + 0*PL_ + r*KSTR + c, g_k_hi + go);
                cp16(d + 1*PL_ + r*KSTR + c, g_k_lo + go);
                cp16(d + 2*PL_ + r*KSTR + c, g_v_hi + go);
                cp16(d + 3*PL_ + r*KSTR + c, g_v_lo + go);
            }
            cpcommit();
            cpwait1();
        } else {
            cpwait0();
        }
        __syncthreads();

        __nv_bfloat16* Kh = stc;
        __nv_bfloat16* Kl = stc + PL_;
        __nv_bfloat16* Vh = stc + 2*PL_;
        __nv_bfloat16* Vl = stc + 3*PL_;

        // ---- S = Q K^T (compensated) ----
        float s[8][4];
        #pragma unroll
        for (int j = 0; j < 8; j++)
            #pragma unroll
            for (int f = 0; f < 4; f++) s[j][f] = 0.f;

        #pragma unroll
        for (int kc = 0; kc < 4; kc++) {
            uint32_t kbh[4][4], kbl[4][4];
            #pragma unroll
            for (int j2 = 0; j2 < 4; j2++) {
                const uint32_t off = (16*j2 + krow)*KSTR + kc*16 + kcsel;
                ldmx4(kbh[j2], smem_u32(Kh + off));
                ldmx4(kbl[j2], smem_u32(Kl + off));
            }
            #pragma unroll
            for (int j2 = 0; j2 < 4; j2++) {
                mma16816(s[2*j2],   qh[kc], &kbh[j2][0]);
                mma16816(s[2*j2],   qh[kc], &kbl[j2][0]);
                mma16816(s[2*j2],   ql[kc], &kbh[j2][0]);
                mma16816(s[2*j2+1], qh[kc], &kbh[j2][2]);
                mma16816(s[2*j2+1], qh[kc], &kbl[j2][2]);
                mma16816(s[2*j2+1], ql[kc], &kbh[j2][2]);
            }
        }

        // ---- online softmax on fragments ----
        #pragma unroll
        for (int r = 0; r < 2; r++) {
            float mx = -1e30f;
            #pragma unroll
            for (int j = 0; j < 8; j++)
                mx = fmaxf(mx, fmaxf(s[j][2*r], s[j][2*r+1]));
            mx *= 0.125f;
            mx = fmaxf(mx, __shfl_xor_sync(0xffffffffu, mx, 1));
            mx = fmaxf(mx, __shfl_xor_sync(0xffffffffu, mx, 2));
            const float mnew = fmaxf(m_run[r], mx);
            const float corr = __expf(m_run[r] - mnew);
            m_run[r] = mnew;
            float rs = 0.f;
            #pragma unroll
            for (int j = 0; j < 8; j++) {
                float p0 = __expf(fmaf(s[j][2*r],   0.125f, -mnew));
                float p1 = __expf(fmaf(s[j][2*r+1], 0.125f, -mnew));
                s[j][2*r] = p0; s[j][2*r+1] = p1;
                rs += p0 + p1;
            }
            rs += __shfl_xor_sync(0xffffffffu, rs, 1);
            rs += __shfl_xor_sync(0xffffffffu, rs, 2);
            l_run[r] = l_run[r] * corr + rs;
            #pragma unroll
            for (int j = 0; j < 8; j++) { o[j][2*r] *= corr; o[j][2*r+1] *= corr; }
        }

        // ---- O += P V (compensated) ----
        #pragma unroll
        for (int kc = 0; kc < 4; kc++) {
            uint32_t ph[4], pl[4];
            pack2(s[2*kc][0],   s[2*kc][1],   ph[0], pl[0]);
            pack2(s[2*kc][2],   s[2*kc][3],   ph[1], pl[1]);
            pack2(s[2*kc+1][0], s[2*kc+1][1], ph[2], pl[2]);
            pack2(s[2*kc+1][2], s[2*kc+1][3], ph[3], pl[3]);

            uint32_t vbh[4][4], vbl[4][4];
            #pragma unroll
            for (int j2 = 0; j2 < 4; j2++) {
                const uint32_t off = (16*kc + vrow)*KSTR + 16*j2 + vcsel;
                ldmx4t(vbh[j2], smem_u32(Vh + off));
                ldmx4t(vbl[j2], smem_u32(Vl + off));
            }
            #pragma unroll
            for (int j2 = 0; j2 < 4; j2++) {
                mma16816(o[2*j2],   ph, &vbh[j2][0]);
                mma16816(o[2*j2],   ph, &vbl[j2][0]);
                mma16816(o[2*j2],   pl, &vbh[j2][0]);
                mma16816(o[2*j2+1], ph, &vbh[j2][2]);
                mma16816(o[2*j2+1], ph, &vbl[j2][2]);
                mma16816(o[2*j2+1], pl, &vbh[j2][2]);
            }
        }
        __syncthreads();   // stage cur free before next iteration's prefetch
    }

    // ---- epilogue: normalize + write [B,S,D] ----
    const int bb = bh >> 4, hh = bh & 15;
    #pragma unroll
    for (int r = 0; r < 2; r++) {
        const float inv = 1.f / l_run[r];
        const int row = qbase + 16*w + g + 8*r;
        float* yp = g_y + ((size_t)(bb * S_ + row)) * D_ + hh * HD_;
        #pragma unroll
        for (int j = 0; j < 8; j++) {
            float2 v;
            v.x = o[j][2*r]   * inv;
            v.y = o[j][2*r+1] * inv;
            *(float2*)(yp + 8*j + 2*lmb) = v;
        }
    }
}

// ===========================================================================
extern "C" void kernel_launch(void* const* d_in, const int* in_sizes, int n_in,
                              void* d_out, int out_size)
{
    const float* q  = (const float*)d_in[0];
    const float* k  = (const float*)d_in[1];
    const float* v  = (const float*)d_in[2];
    const float* Wq = (const float*)d_in[3];
    const float* bq = (const float*)d_in[4];
    const float* Wk = (const float*)d_in[5];
    const float* bk = (const float*)d_in[6];
    const float* Wv = (const float*)d_in[7];
    const float* bv = (const float*)d_in[8];
    const float* Wo = (const float*)d_in[9];
    const float* bo = (const float*)d_in[10];
    float* out = (float*)d_out;

    __nv_bfloat16 *qhi, *qlo, *khi, *klo, *vhi, *vlo;
    float* gy;
    cudaGetSymbolAddress((void**)&qhi, g_q_hi);
    cudaGetSymbolAddress((void**)&qlo, g_q_lo);
    cudaGetSymbolAddress((void**)&khi, g_k_hi);
    cudaGetSymbolAddress((void**)&klo, g_k_lo);
    cudaGetSymbolAddress((void**)&vhi, g_v_hi);
    cudaGetSymbolAddress((void**)&vlo, g_v_lo);
    cudaGetSymbolAddress((void**)&gy,  g_y);

    const int ASMEM = 2 * STAGE_ * (int)sizeof(__nv_bfloat16);   // 73728 B
    static bool attr_done = false;
    if (!attr_done) {
        cudaFuncSetAttribute(attn_mma, cudaFuncAttributeMaxDynamicSharedMemorySize, ASMEM);
        attr_done = true;
    }

    dim3 gridP(D_ / 128, NROWS / 128);   // (8, 64)
    proj_mma<true><<<gridP, 256>>>(q, Wq, bq, nullptr, qhi, qlo);
    proj_mma<true><<<gridP, 256>>>(k, Wk, bk, nullptr, khi, klo);
    proj_mma<true><<<gridP, 256>>>(v, Wv, bv, nullptr, vhi, vlo);

    attn_mma<<<dim3(S_/64, B_*H_), 128, ASMEM>>>();

    proj_mma<false><<<gridP, 256>>>(gy, Wo, bo, out, nullptr, nullptr);
}

// round 8
// speedup vs baseline: 3.6305x; 1.0873x over previous
#include <cuda_runtime.h>
#include <cuda_bf16.h>
#include <math.h>
#include <stdint.h>

#define B_  4
#define S_  2048
#define D_  1024
#define H_  16
#define HD_ 64
#define NROWS (B_*S_)                       // 8192
#define NPLANE ((size_t)B_*H_*S_*HD_)       // 8388608

// Scratch (allocation-free)
__device__ __align__(16) __nv_bfloat16 g_q_hi[NPLANE], g_q_lo[NPLANE];
__device__ __align__(16) __nv_bfloat16 g_k_hi[NPLANE], g_k_lo[NPLANE];
__device__ __align__(16) __nv_bfloat16 g_v_hi[NPLANE], g_v_lo[NPLANE];
__device__ __align__(16) __nv_bfloat16 g_xh[(size_t)NROWS*D_], g_xl[(size_t)NROWS*D_];
__device__ __align__(16) __nv_bfloat16 g_wh[(size_t)D_*D_],    g_wl[(size_t)D_*D_];
__device__ __align__(16) __nv_bfloat16 g_yh[(size_t)NROWS*D_], g_yl[(size_t)NROWS*D_];

// ---------------------------------------------------------------------------
// Helpers (baseline PTX only — no arch-specific instructions)
// ---------------------------------------------------------------------------
__device__ __forceinline__ uint32_t smem_u32(const void* p) {
    return (uint32_t)__cvta_generic_to_shared(p);
}
__device__ __forceinline__ void ldmx4(uint32_t* d, uint32_t addr) {
    asm volatile("ldmatrix.sync.aligned.m8n8.x4.shared.b16 {%0,%1,%2,%3}, [%4];"
                 : "=r"(d[0]), "=r"(d[1]), "=r"(d[2]), "=r"(d[3]) : "r"(addr));
}
__device__ __forceinline__ void ldmx4t(uint32_t* d, uint32_t addr) {
    asm volatile("ldmatrix.sync.aligned.m8n8.x4.trans.shared.b16 {%0,%1,%2,%3}, [%4];"
                 : "=r"(d[0]), "=r"(d[1]), "=r"(d[2]), "=r"(d[3]) : "r"(addr));
}
__device__ __forceinline__ void ldmx2(uint32_t* d, uint32_t addr) {
    asm volatile("ldmatrix.sync.aligned.m8n8.x2.shared.b16 {%0,%1}, [%2];"
                 : "=r"(d[0]), "=r"(d[1]) : "r"(addr));
}
__device__ __forceinline__ void mma16816(float* c, const uint32_t* a, const uint32_t* b) {
    asm volatile("mma.sync.aligned.m16n8k16.row.col.f32.bf16.bf16.f32 "
                 "{%0,%1,%2,%3}, {%4,%5,%6,%7}, {%8,%9}, {%0,%1,%2,%3};"
                 : "+f"(c[0]), "+f"(c[1]), "+f"(c[2]), "+f"(c[3])
                 : "r"(a[0]), "r"(a[1]), "r"(a[2]), "r"(a[3]), "r"(b[0]), "r"(b[1]));
}
__device__ __forceinline__ void cp16(uint32_t dst, const void* src) {
    asm volatile("cp.async.cg.shared.global [%0], [%1], 16;" :: "r"(dst), "l"(src));
}
__device__ __forceinline__ void cp16p(void* dst, const void* src) {
    asm volatile("cp.async.cg.shared.global [%0], [%1], 16;"
                 :: "r"(smem_u32(dst)), "l"(src));
}
__device__ __forceinline__ void cpcommit() { asm volatile("cp.async.commit_group;"); }
__device__ __forceinline__ void cpwait0()  { asm volatile("cp.async.wait_group 0;"); }
__device__ __forceinline__ void cpwait1()  { asm volatile("cp.async.wait_group 1;"); }
__device__ __forceinline__ void cpwait2()  { asm volatile("cp.async.wait_group 2;"); }

__device__ __forceinline__ void pack2(float a, float b, uint32_t& hi, uint32_t& lo) {
    __nv_bfloat162 h = __floats2bfloat162_rn(a, b);
    float ra = a - __bfloat162float(h.x);
    float rb = b - __bfloat162float(h.y);
    __nv_bfloat162 l2 = __floats2bfloat162_rn(ra, rb);
    hi = *(uint32_t*)&h; lo = *(uint32_t*)&l2;
}

#define SWZ128(x) ((x) ^ (((x) >> 3) & 0x70))

// ===========================================================================
// split: fp32 array -> bf16 hi/lo planes (elementwise, memory bound)
// ===========================================================================
__global__ __launch_bounds__(256)
void split_kernel(const float* __restrict__ x, __nv_bfloat16* __restrict__ hp,
                  __nv_bfloat16* __restrict__ lp, int n4)
{
    int i = blockIdx.x * blockDim.x + threadIdx.x;
    if (i >= n4) return;
    float4 v = ((const float4*)x)[i];
    uint32_t h0, l0, h1, l1;
    pack2(v.x, v.y, h0, l0);
    pack2(v.z, v.w, h1, l1);
    ((uint2*)hp)[i] = make_uint2(h0, h1);
    ((uint2*)lp)[i] = make_uint2(l0, l1);
}

// ===========================================================================
// Projection GEMM v2 (legacy mma.sync): out = relu(A @ W^T + b)
// Inputs are pre-split bf16 hi/lo planes. CTA 128x128, 256 thr, warp 64x32.
// K-chunks of 64, 3-stage cp.async pipeline, SW128-swizzled smem.
// SPLIT=true: write bf16 hi/lo planes head-split; else fp32 row-major.
// ===========================================================================
#define PPLANE_ 16384                 // 128 rows * 128 B
#define PSTG_   (4*PPLANE_)           // 65536 B per stage (Ah,Al,Bh,Bl)
#define PNKC_   (D_/64)               // 16 chunks
#define PROJ_SMEM (3*PSTG_ + 1024)

template<bool SPLIT>
__global__ __launch_bounds__(256)
void proj_mma2(const __nv_bfloat16* __restrict__ Xh, const __nv_bfloat16* __restrict__ Xl,
               const __nv_bfloat16* __restrict__ Wh, const __nv_bfloat16* __restrict__ Wl,
               const float* __restrict__ bias, float* __restrict__ outF,
               __nv_bfloat16* __restrict__ hiP, __nv_bfloat16* __restrict__ loP)
{
    extern __shared__ char dsm_raw[];
    const uint32_t dbase = (smem_u32(dsm_raw) + 1023) & ~1023u;

    const int t = threadIdx.x, lane = t & 31, warp = t >> 5;
    const int wm = warp & 1, wn = warp >> 1;
    const int rowBase = blockIdx.y * 128, colBase = blockIdx.x * 128;

    // loader mapping: row = t>>1 (0..127), 4 x 16B units per plane
    const int ldr = t >> 1;
    const int ldc0 = (t & 1) * 4;              // 16B-unit index base (0 or 4)
    const __nv_bfloat16* xp = Xh + (size_t)(rowBase + ldr) * D_;
    const __nv_bfloat16* xq = Xl + (size_t)(rowBase + ldr) * D_;
    const __nv_bfloat16* wp = Wh + (size_t)(colBase + ldr) * D_;
    const __nv_bfloat16* wq = Wl + (size_t)(colBase + ldr) * D_;
    const uint32_t rb = (uint32_t)ldr * 128;

    auto load_chunk = [&](int chunk, uint32_t stg) {
        const int k0 = chunk * 64;
        #pragma unroll
        for (int u = 0; u < 4; u++) {
            const int c16 = ldc0 + u;
            const uint32_t so = SWZ128(rb + c16 * 16);
            const int ge = k0 + c16 * 8;
            cp16(stg + 0*PPLANE_ + so, xp + ge);
            cp16(stg + 1*PPLANE_ + so, xq + ge);
            cp16(stg + 2*PPLANE_ + so, wp + ge);
            cp16(stg + 3*PPLANE_ + so, wq + ge);
        }
        cpcommit();
    };

    load_chunk(0, dbase + 0*PSTG_);
    load_chunk(1, dbase + 1*PSTG_);
    load_chunk(2, dbase + 2*PSTG_);

    float acc[4][4][4];
    #pragma unroll
    for (int i = 0; i < 4; i++)
        #pragma unroll
        for (int j = 0; j < 4; j++)
            #pragma unroll
            for (int f = 0; f < 4; f++) acc[i][j][f] = 0.f;

    const uint32_t arow = (uint32_t)(wm*64 + (lane & 15));
    const uint32_t acolu = (uint32_t)(lane >> 4);            // 0..1 (16B unit within k-step)
    const uint32_t brow = (uint32_t)(wn*32 + (lane & 7));
    const uint32_t bcolu = (uint32_t)((lane >> 3) & 1);

    for (int it = 0; it < PNKC_; it++) {
        const uint32_t stg = dbase + (uint32_t)(it % 3) * PSTG_;

        if (it <= PNKC_ - 3)      cpwait2();
        else if (it == PNKC_ - 2) cpwait1();
        else                      cpwait0();
        __syncthreads();

        const uint32_t Ah = stg, Al = stg + PPLANE_;
        const uint32_t Bh = stg + 2*PPLANE_, Bl = stg + 3*PPLANE_;

        #pragma unroll
        for (int ks = 0; ks < 4; ks++) {
            uint32_t ah[4][4], al[4][4], bh[4][2], bl[4][2];
            #pragma unroll
            for (int i = 0; i < 4; i++) {
                const uint32_t off = SWZ128((arow + i*16)*128 + ks*32 + acolu*16);
                ldmx4(ah[i], Ah + off);
                ldmx4(al[i], Al + off);
            }
            #pragma unroll
            for (int j = 0; j < 4; j++) {
                const uint32_t off = SWZ128((brow + j*8)*128 + ks*32 + bcolu*16);
                ldmx2(bh[j], Bh + off);
                ldmx2(bl[j], Bl + off);
            }
            #pragma unroll
            for (int i = 0; i < 4; i++)
                #pragma unroll
                for (int j = 0; j < 4; j++) {
                    mma16816(acc[i][j], ah[i], bh[j]);
                    mma16816(acc[i][j], ah[i], bl[j]);
                    mma16816(acc[i][j], al[i], bh[j]);
                }
        }
        __syncthreads();
        if (it + 3 < PNKC_) load_chunk(it + 3, stg);
    }

    // epilogue: bias + relu (+ hi/lo split for SPLIT path)
    const int g = lane >> 2, lmb = lane & 3;
    #pragma unroll
    for (int i = 0; i < 4; i++)
        #pragma unroll
        for (int j = 0; j < 4; j++) {
            const int col = colBase + wn*32 + j*8 + lmb*2;
            const float b0 = bias[col], b1 = bias[col+1];
            #pragma unroll
            for (int r = 0; r < 2; r++) {
                const int row = rowBase + wm*64 + i*16 + g + 8*r;
                float v0 = acc[i][j][2*r+0] + b0;  v0 = fmaxf(v0, 0.f);
                float v1 = acc[i][j][2*r+1] + b1;  v1 = fmaxf(v1, 0.f);
                if (SPLIT) {
                    uint32_t hi, lo; pack2(v0, v1, hi, lo);
                    const int hh = col >> 6, hd = col & 63;
                    const int bb = row >> 11, ss = row & (S_ - 1);
                    const size_t idx = ((size_t)((bb*H_ + hh)*S_) + ss)*HD_ + hd;
                    *(uint32_t*)(hiP + idx) = hi;
                    *(uint32_t*)(loP + idx) = lo;
                } else {
                    float2 o; o.x = v0; o.y = v1;
                    *(float2*)(outF + (size_t)row * D_ + col) = o;
                }
            }
        }
}

// ===========================================================================
// Flash attention on tensor cores (R6-proven; epilogue writes hi/lo planes).
// ===========================================================================
#define KSTR 72
#define PL_  (64*KSTR)
#define STAGE_ (4*PL_)
#define NT_ (S_/64)
#define ATTN_SMEM (2*STAGE_*(int)sizeof(__nv_bfloat16))

__global__ __launch_bounds__(128)
void attn_mma()
{
    extern __shared__ __nv_bfloat16 sm[];
    const int t = threadIdx.x, lane = t & 31, w = t >> 5;
    const int bh = blockIdx.y, qbase = blockIdx.x * 64;
    const int g = lane >> 2, lmb = lane & 3;

    __nv_bfloat16* st0 = sm;
    __nv_bfloat16* st1 = sm + STAGE_;
    const size_t base = (size_t)bh * S_;

    #pragma unroll
    for (int i = 0; i < 4; i++) {
        const int id = t + 128*i, r = id >> 3, c = (id & 7) * 8;
        const size_t go = (base + r) * HD_ + c;
        cp16p(st0 + 0*PL_ + r*KSTR + c, g_k_hi + go);
        cp16p(st0 + 1*PL_ + r*KSTR + c, g_k_lo + go);
        cp16p(st0 + 2*PL_ + r*KSTR + c, g_v_hi + go);
        cp16p(st0 + 3*PL_ + r*KSTR + c, g_v_lo + go);
    }
    cpcommit();
    #pragma unroll
    for (int i = 0; i < 4; i++) {
        const int id = t + 128*i, r = id >> 3, c = (id & 7) * 8;
        const size_t go = (base + qbase + r) * HD_ + c;
        cp16p(st1 + 0*PL_ + r*KSTR + c, g_q_hi + go);
        cp16p(st1 + 1*PL_ + r*KSTR + c, g_q_lo + go);
    }
    cpcommit();
    cpwait0();
    __syncthreads();

    uint32_t qh[4][4], ql[4][4];
    {
        const int arow = 16*w + (lane & 15);
        const int acol = (lane >> 4) * 8;
        #pragma unroll
        for (int kc = 0; kc < 4; kc++) {
            ldmx4(qh[kc], smem_u32(st1 + 0*PL_ + arow*KSTR + kc*16 + acol));
            ldmx4(ql[kc], smem_u32(st1 + 1*PL_ + arow*KSTR + kc*16 + acol));
        }
    }
    __syncthreads();

    float o[8][4];
    #pragma unroll
    for (int j = 0; j < 8; j++)
        #pragma unroll
        for (int f = 0; f < 4; f++) o[j][f] = 0.f;
    float m_run[2] = {-1e30f, -1e30f}, l_run[2] = {0.f, 0.f};

    const int krow = (lane & 7) + ((lane >> 4) & 1) * 8;
    const int kcsel = ((lane >> 3) & 1) * 8;
    const int vrow = lane & 15;
    const int vcsel = ((lane >> 4) & 1) * 8;

    for (int it = 0; it < NT_; it++) {
        const int cur = it & 1;
        __nv_bfloat16* stc = cur ? st1 : st0;
        if (it + 1 < NT_) {
            __nv_bfloat16* d = cur ? st0 : st1;
            #pragma unroll
            for (int i = 0; i < 4; i++) {
                const int id = t + 128*i, r = id >> 3, c = (id & 7) * 8;
                const size_t go = (base + (size_t)(it+1)*64 + r) * HD_ + c;
                cp16p(d + 0*PL_ + r*KSTR + c, g_k_hi + go);
                cp16p(d + 1*PL_ + r*KSTR + c, g_k_lo + go);
                cp16p(d + 2*PL_ + r*KSTR + c, g_v_hi + go);
                cp16p(d + 3*PL_ + r*KSTR + c, g_v_lo + go);
            }
            cpcommit();
            cpwait1();
        } else {
            cpwait0();
        }
        __syncthreads();

        __nv_bfloat16* Kh = stc;
        __nv_bfloat16* Kl = stc + PL_;
        __nv_bfloat16* Vh = stc + 2*PL_;
        __nv_bfloat16* Vl = stc + 3*PL_;

        float s[8][4];
        #pragma unroll
        for (int j = 0; j < 8; j++)
            #pragma unroll
            for (int f = 0; f < 4; f++) s[j][f] = 0.f;

        #pragma unroll
        for (int kc = 0; kc < 4; kc++) {
            uint32_t kbh[4][4], kbl[4][4];
            #pragma unroll
            for (int j2 = 0; j2 < 4; j2++) {
                const uint32_t off = (16*j2 + krow)*KSTR + kc*16 + kcsel;
                ldmx4(kbh[j2], smem_u32(Kh + off));
                ldmx4(kbl[j2], smem_u32(Kl + off));
            }
            #pragma unroll
            for (int j2 = 0; j2 < 4; j2++) {
                mma16816(s[2*j2],   qh[kc], &kbh[j2][0]);
                mma16816(s[2*j2],   qh[kc], &kbl[j2][0]);
                mma16816(s[2*j2],   ql[kc], &kbh[j2][0]);
                mma16816(s[2*j2+1], qh[kc], &kbh[j2][2]);
                mma16816(s[2*j2+1], qh[kc], &kbl[j2][2]);
                mma16816(s[2*j2+1], ql[kc], &kbh[j2][2]);
            }
        }

        #pragma unroll
        for (int r = 0; r < 2; r++) {
            float mx = -1e30f;
            #pragma unroll
            for (int j = 0; j < 8; j++)
                mx = fmaxf(mx, fmaxf(s[j][2*r], s[j][2*r+1]));
            mx *= 0.125f;
            mx = fmaxf(mx, __shfl_xor_sync(0xffffffffu, mx, 1));
            mx = fmaxf(mx, __shfl_xor_sync(0xffffffffu, mx, 2));
            const float mnew = fmaxf(m_run[r], mx);
            const float corr = __expf(m_run[r] - mnew);
            m_run[r] = mnew;
            float rs = 0.f;
            #pragma unroll
            for (int j = 0; j < 8; j++) {
                float p0 = __expf(fmaf(s[j][2*r],   0.125f, -mnew));
                float p1 = __expf(fmaf(s[j][2*r+1], 0.125f, -mnew));
                s[j][2*r] = p0; s[j][2*r+1] = p1;
                rs += p0 + p1;
            }
            rs += __shfl_xor_sync(0xffffffffu, rs, 1);
            rs += __shfl_xor_sync(0xffffffffu, rs, 2);
            l_run[r] = l_run[r] * corr + rs;
            #pragma unroll
            for (int j = 0; j < 8; j++) { o[j][2*r] *= corr; o[j][2*r+1] *= corr; }
        }

        #pragma unroll
        for (int kc = 0; kc < 4; kc++) {
            uint32_t ph[4], pl[4];
            pack2(s[2*kc][0],   s[2*kc][1],   ph[0], pl[0]);
            pack2(s[2*kc][2],   s[2*kc][3],   ph[1], pl[1]);
            pack2(s[2*kc+1][0], s[2*kc+1][1], ph[2], pl[2]);
            pack2(s[2*kc+1][2], s[2*kc+1][3], ph[3], pl[3]);

            uint32_t vbh[4][4], vbl[4][4];
            #pragma unroll
            for (int j2 = 0; j2 < 4; j2++) {
                const uint32_t off = (16*kc + vrow)*KSTR + 16*j2 + vcsel;
                ldmx4t(vbh[j2], smem_u32(Vh + off));
                ldmx4t(vbl[j2], smem_u32(Vl + off));
            }
            #pragma unroll
            for (int j2 = 0; j2 < 4; j2++) {
                mma16816(o[2*j2],   ph, &vbh[j2][0]);
                mma16816(o[2*j2],   ph, &vbl[j2][0]);
                mma16816(o[2*j2],   pl, &vbh[j2][0]);
                mma16816(o[2*j2+1], ph, &vbh[j2][2]);
                mma16816(o[2*j2+1], ph, &vbl[j2][2]);
                mma16816(o[2*j2+1], pl, &vbh[j2][2]);
            }
        }
        __syncthreads();
    }

    // epilogue: normalize + write y hi/lo planes [B,S,D]
    const int bb = bh >> 4, hh = bh & 15;
    #pragma unroll
    for (int r = 0; r < 2; r++) {
        const float inv = 1.f / l_run[r];
        const int row = qbase + 16*w + g + 8*r;
        const size_t iy = ((size_t)(bb * S_ + row)) * D_ + hh * HD_ + 2*lmb;
        #pragma unroll
        for (int j = 0; j < 8; j++) {
            uint32_t hi, lo;
            pack2(o[j][2*r] * inv, o[j][2*r+1] * inv, hi, lo);
            *(uint32_t*)(g_yh + iy + 8*j) = hi;
            *(uint32_t*)(g_yl + iy + 8*j) = lo;
        }
    }
}

// ===========================================================================
extern "C" void kernel_launch(void* const* d_in, const int* in_sizes, int n_in,
                              void* d_out, int out_size)
{
    const float* q  = (const float*)d_in[0];
    const float* k  = (const float*)d_in[1];
    const float* v  = (const float*)d_in[2];
    const float* Wq = (const float*)d_in[3];
    const float* bq = (const float*)d_in[4];
    const float* Wk = (const float*)d_in[5];
    const float* bk = (const float*)d_in[6];
    const float* Wv = (const float*)d_in[7];
    const float* bv = (const float*)d_in[8];
    const float* Wo = (const float*)d_in[9];
    const float* bo = (const float*)d_in[10];
    float* out = (float*)d_out;

    __nv_bfloat16 *qhi, *qlo, *khi, *klo, *vhi, *vlo, *xh, *xl, *wh, *wl, *yh, *yl;
    cudaGetSymbolAddress((void**)&qhi, g_q_hi);
    cudaGetSymbolAddress((void**)&qlo, g_q_lo);
    cudaGetSymbolAddress((void**)&khi, g_k_hi);
    cudaGetSymbolAddress((void**)&klo, g_k_lo);
    cudaGetSymbolAddress((void**)&vhi, g_v_hi);
    cudaGetSymbolAddress((void**)&vlo, g_v_lo);
    cudaGetSymbolAddress((void**)&xh,  g_xh);
    cudaGetSymbolAddress((void**)&xl,  g_xl);
    cudaGetSymbolAddress((void**)&wh,  g_wh);
    cudaGetSymbolAddress((void**)&wl,  g_wl);
    cudaGetSymbolAddress((void**)&yh,  g_yh);
    cudaGetSymbolAddress((void**)&yl,  g_yl);

    static bool attr_done = false;
    if (!attr_done) {
        cudaFuncSetAttribute(attn_mma, cudaFuncAttributeMaxDynamicSharedMemorySize, ATTN_SMEM);
        cudaFuncSetAttribute(proj_mma2<true>,  cudaFuncAttributeMaxDynamicSharedMemorySize, PROJ_SMEM);
        cudaFuncSetAttribute(proj_mma2<false>, cudaFuncAttributeMaxDynamicSharedMemorySize, PROJ_SMEM);
        attr_done = true;
    }

    const int NX4 = NROWS * D_ / 4;   // 2097152
    const int NW4 = D_ * D_ / 4;      // 262144
    dim3 gridP(D_ / 128, NROWS / 128);   // (8, 64)

    // Q projection
    split_kernel<<<(NX4 + 255)/256, 256>>>(q,  xh, xl, NX4);
    split_kernel<<<(NW4 + 255)/256, 256>>>(Wq, wh, wl, NW4);
    proj_mma2<true><<<gridP, 256, PROJ_SMEM>>>(xh, xl, wh, wl, bq, nullptr, qhi, qlo);
    // K projection
    split_kernel<<<(NX4 + 255)/256, 256>>>(k,  xh, xl, NX4);
    split_kernel<<<(NW4 + 255)/256, 256>>>(Wk, wh, wl, NW4);
    proj_mma2<true><<<gridP, 256, PROJ_SMEM>>>(xh, xl, wh, wl, bk, nullptr, khi, klo);
    // V projection
    split_kernel<<<(NX4 + 255)/256, 256>>>(v,  xh, xl, NX4);
    split_kernel<<<(NW4 + 255)/256, 256>>>(Wv, wh, wl, NW4);
    proj_mma2<true><<<gridP, 256, PROJ_SMEM>>>(xh, xl, wh, wl, bv, nullptr, vhi, vlo);

    attn_mma<<<dim3(S_/64, B_*H_), 128, ATTN_SMEM>>>();

    // Output projection (consumes y planes written by attn)
    split_kernel<<<(NW4 + 255)/256, 256>>>(Wo, wh, wl, NW4);
    proj_mma2<false><<<gridP, 256, PROJ_SMEM>>>(yh, yl, wh, wl, bo, out, nullptr, nullptr);
}